// round 14
// baseline (speedup 1.0000x reference)
#include <cuda_runtime.h>
#include <cuda_bf16.h>
#include <cstdint>

#define B_DIM 4096
#define IN_DIM 2048
#define F_DIM 4096

// ---------------------------------------------------------------------------
// Scratch (device globals: no allocation allowed)
// ---------------------------------------------------------------------------
__device__ float          g_xr[B_DIM * IN_DIM];    // rotated activations (fp32 — REQUIRED)
__device__ float          g_wr[IN_DIM * F_DIM];    // rotated weights (fp32 — REQUIRED)
__device__ __nv_bfloat16  g_xq[B_DIM * IN_DIM];    // quantized activations [M][K]
__device__ __nv_bfloat16  g_wqT[F_DIM * IN_DIM];   // quantized weights TRANSPOSED [N][K]
__device__ float          g_yr[B_DIM * F_DIM];     // GEMM result (float, exact ints)
__device__ int            g_maxx_bits;
__device__ int            g_maxw_bits;

// ===========================================================================
// Helpers
// ===========================================================================
__device__ __forceinline__ uint32_t smem_u32(const void* p) {
    uint32_t a;
    asm("{ .reg .u64 t; cvta.to.shared.u64 t, %1; cvt.u32.u64 %0, t; }" : "=r"(a) : "l"(p));
    return a;
}

__device__ __forceinline__ void cpasync16(uint32_t dst, const void* src) {
    asm volatile("cp.async.cg.shared.global [%0], [%1], 16;\n" :: "r"(dst), "l"(src));
}

// Swizzle<3,4,3>: XOR 16B-chunk bits [6:4] with 128B-line bits [9:7]
__device__ __forceinline__ uint32_t swz(uint32_t o) { return o ^ (((o >> 7) & 7) << 4); }

__device__ __forceinline__ void ldsm_x4(uint32_t r[4], uint32_t addr) {
    asm volatile("ldmatrix.sync.aligned.m8n8.x4.shared.b16 {%0,%1,%2,%3}, [%4];"
                 : "=r"(r[0]), "=r"(r[1]), "=r"(r[2]), "=r"(r[3]) : "r"(addr));
}

__device__ __forceinline__ void mma_bf16(float c[4], const uint32_t a[4], uint32_t b0, uint32_t b1) {
    asm volatile(
        "mma.sync.aligned.m16n8k16.row.col.f32.bf16.bf16.f32 "
        "{%0,%1,%2,%3}, {%4,%5,%6,%7}, {%8,%9}, {%0,%1,%2,%3};"
        : "+f"(c[0]), "+f"(c[1]), "+f"(c[2]), "+f"(c[3])
        : "r"(a[0]), "r"(a[1]), "r"(a[2]), "r"(a[3]), "r"(b0), "r"(b1));
}

// ===========================================================================
// WHT primitives
// ===========================================================================
__device__ __forceinline__ void wht64(float v[64]) {
#pragma unroll
    for (int s = 1; s < 64; s <<= 1) {
#pragma unroll
        for (int i = 0; i < 64; i++) {
            if ((i & s) == 0) {
                float a = v[i], b = v[i + s];
                v[i]     = a + b;
                v[i + s] = a - b;
            }
        }
    }
}

__global__ void init_kernel() {
    g_maxx_bits = 0;
    g_maxw_bits = 0;
}

// ---------------------------------------------------------------------------
// FUSED column-axis WHT-4096 (8 cols / 512 threads / 128 KB smem)
// ---------------------------------------------------------------------------
#define FSWZ(a) ((a) ^ ((((a) >> 9) & 3) << 3))

template <bool DO_MAX, bool FINAL>
__global__ __launch_bounds__(512) void colwht_fused8_kernel(const float* __restrict__ in,
                                                            float* __restrict__ out,
                                                            int ncols,
                                                            const float* __restrict__ bias) {
    extern __shared__ float sm[];
    int tid  = threadIdx.x;
    int col0 = blockIdx.x * 8;

#pragma unroll
    for (int j = 0; j < 16; j++) {
        int i = tid + j * 512;
        int r = i >> 1, q = i & 1;
        float4 v = *(const float4*)&in[(size_t)r * ncols + col0 + q * 4];
        *(float4*)&sm[FSWZ(r * 8 + q * 4)] = v;
    }
    __syncthreads();

    int g = tid >> 3, c = tid & 7;
    float v[64];

#pragma unroll
    for (int k = 0; k < 64; k++) v[k] = sm[FSWZ((g * 64 + k) * 8 + c)];
    wht64(v);
#pragma unroll
    for (int k = 0; k < 64; k++) sm[FSWZ((g * 64 + k) * 8 + c)] = v[k];
    __syncthreads();

#pragma unroll
    for (int k = 0; k < 64; k++) v[k] = sm[FSWZ((g + 64 * k) * 8 + c)];
    wht64(v);

    if (DO_MAX) {
        float m = 0.f;
#pragma unroll
        for (int k = 0; k < 64; k++) m = fmaxf(m, fabsf(v[k]));
#pragma unroll
        for (int off = 16; off; off >>= 1)
            m = fmaxf(m, __shfl_xor_sync(0xffffffffu, m, off));
        if ((tid & 31) == 0) atomicMax(&g_maxx_bits, __float_as_int(m));
    }

    float scale = 1.f, bv = 0.f;
    if (FINAL) {
        float mx = __int_as_float(g_maxx_bits);
        float mw = __int_as_float(g_maxw_bits);
        scale = (mx / 127.f) * (mw / 127.f) * 0x1p-24f;
        bv    = bias[col0 + c];
    }
#pragma unroll
    for (int k = 0; k < 64; k++) {
        size_t idx = (size_t)(g + 64 * k) * ncols + col0 + c;
        out[idx] = FINAL ? (v[k] * scale + bv) : v[k];
    }
}

// ---------------------------------------------------------------------------
// PIPELINED row-axis WHT: each block handles 8 rows as 4 pairs with
// double-buffered cp.async staging (64 KB dyn smem). While pair p is
// computed/written, pair p+2 streams in. Butterfly order, swizzles, and
// coalesced writeout identical to the proven kernel -> bit-identical output.
// Safe for in-place (in == out): rows within a block are disjoint.
// ---------------------------------------------------------------------------
template <bool DO_MAXW>
__global__ __launch_bounds__(128) void rowwht_pipe_kernel(const float* __restrict__ in,
                                                          float* __restrict__ out) {
    extern __shared__ float st[];          // [2 bufs][2 rows][4096]
    uint32_t sb = smem_u32(st);
    int tid = threadIdx.x;
    int g   = tid >> 6;                    // row within pair
    int t   = tid & 63;
    size_t base = (size_t)blockIdx.x * 8;  // first row of this block

    auto prefetch = [&](int buf, int pair) {
#pragma unroll
        for (int j = 0; j < 16; j++) {
            int c   = tid + j * 128;       // 0..2047 chunks of 16B
            int rl  = c >> 10;             // row-local (1024 chunks per row)
            int off = (c & 1023) * 4;      // float offset
            cpasync16(sb + (uint32_t)(((buf * 2 + rl) * 4096 + off) * 4),
                      in + (base + (size_t)pair * 2 + rl) * 4096 + off);
        }
        asm volatile("cp.async.commit_group;\n");
    };

    prefetch(0, 0);
    prefetch(1, 1);

    float m = 0.f;
#pragma unroll
    for (int p = 0; p < 4; p++) {
        if (p < 3) asm volatile("cp.async.wait_group 1;\n");
        else       asm volatile("cp.async.wait_group 0;\n");
        __syncthreads();

        int buf  = p & 1;
        float* S = st + (buf * 2 + g) * 4096;
        float v[64];

        // pass 1: elements t + 64k (linear layout from cp.async)
#pragma unroll
        for (int k = 0; k < 64; k++) v[k] = S[t + (k << 6)];
        wht64(v);
        __syncthreads();                   // all pass-1 reads done before overwrite
#pragma unroll
        for (int k = 0; k < 64; k++) {
            int a = t + (k << 6);
            S[a ^ ((a >> 6) & 31)] = v[k];
        }
        __syncthreads();

        // pass 2: elements 64t + k
#pragma unroll
        for (int k = 0; k < 64; k++) {
            int a = (t << 6) + k;
            v[k] = S[a ^ ((a >> 6) & 31)];
        }
        wht64(v);
        if (DO_MAXW) {
#pragma unroll
            for (int k = 0; k < 64; k++) m = fmaxf(m, fabsf(v[k]));
        }
        __syncthreads();                   // pass-2 reads done
#pragma unroll
        for (int k = 0; k < 64; k++) {
            int a = (t << 6) + k;
            S[a ^ ((a >> 6) & 31)] = v[k];
        }
        __syncthreads();

        // coalesced writeout of the pair (8192 floats)
        size_t ob = (base + (size_t)p * 2) * 4096;
#pragma unroll
        for (int i = 0; i < 64; i++) {
            int lin = tid + i * 128;
            int rr  = lin >> 12;
            int a   = lin & 4095;
            out[ob + lin] = st[(buf * 2 + rr) * 4096 + (a ^ ((a >> 6) & 31))];
        }
        __syncthreads();                   // writeout reads done before refill
        if (p + 2 < 4) prefetch(buf, p + 2);
    }

    if (DO_MAXW) {
#pragma unroll
        for (int off = 16; off; off >>= 1)
            m = fmaxf(m, __shfl_xor_sync(0xffffffffu, m, off));
        if ((tid & 31) == 0) atomicMax(&g_maxw_bits, __float_as_int(m));
    }
}

// ===========================================================================
// Quantization (fp32 in, bf16 integer-valued out)
// ===========================================================================
__device__ __forceinline__ float stoch_q(float xv, float nv, float s) {
    float xs = xv / s;
    float f  = floorf(xs);
    float q  = f + ((nv < xs - f) ? 1.f : 0.f);
    return fminf(127.f, fmaxf(-127.f, q));
}

__global__ __launch_bounds__(256) void quantx_kernel(const float* __restrict__ xr,
                                                     const float* __restrict__ noise,
                                                     __nv_bfloat16* __restrict__ qo,
                                                     int n4) {
    int i = blockIdx.x * blockDim.x + threadIdx.x;
    if (i >= n4) return;
    float s = __int_as_float(g_maxx_bits) / 127.f;
    float4 x  = ((const float4*)xr)[i];
    float4 nz = ((const float4*)noise)[i];
    __nv_bfloat162 lo = __floats2bfloat162_rn(stoch_q(x.x, nz.x, s), stoch_q(x.y, nz.y, s));
    __nv_bfloat162 hi = __floats2bfloat162_rn(stoch_q(x.z, nz.z, s), stoch_q(x.w, nz.w, s));
    uint2 o;
    o.x = *(uint32_t*)&lo;
    o.y = *(uint32_t*)&hi;
    ((uint2*)qo)[i] = o;
}

// weights: quantize + transpose [IN][F] -> [F][IN] bf16 (K-major B operand)
__global__ __launch_bounds__(256) void quantw_transpose_kernel(const float* __restrict__ wr,
                                                               const float* __restrict__ noise,
                                                               __nv_bfloat16* __restrict__ qoT) {
    __shared__ __nv_bfloat16 t[32][33];
    float s = __int_as_float(g_maxw_bits) / 127.f;
    int x  = blockIdx.x * 32 + threadIdx.x;   // F index
    int y0 = blockIdx.y * 32;                 // IN base
#pragma unroll
    for (int j = 0; j < 4; j++) {
        int y   = y0 + threadIdx.y + j * 8;
        int idx = y * F_DIM + x;
        t[threadIdx.y + j * 8][threadIdx.x] = __float2bfloat16(stoch_q(wr[idx], noise[idx], s));
    }
    __syncthreads();
#pragma unroll
    for (int j = 0; j < 4; j++) {
        int fo = blockIdx.x * 32 + threadIdx.y + j * 8;
        qoT[(size_t)fo * IN_DIM + y0 + threadIdx.x] = t[threadIdx.x][threadIdx.y + j * 8];
    }
}

// ===========================================================================
// Pipelined bf16 GEMM (HMMA), PROVEN config: CTA 128x128, 8 warps (2x4),
// warp tile 64x32, BK=64 (128B rows, SW), 3-stage cp.async, 2 CTAs/SM.
// ===========================================================================
#define GBM 128
#define GBN 128
#define GBK 64
#define NSTAGE 3
#define KT (IN_DIM / GBK)                          // 32
#define STAGE_BYTES ((GBM + GBN) * GBK * 2)        // 32768
#define GEMM_SMEM (NSTAGE * STAGE_BYTES)           // 98304

__global__ __launch_bounds__(256, 2) void gemm_bf16_kernel(const __nv_bfloat16* __restrict__ A,
                                                           const __nv_bfloat16* __restrict__ Bm,
                                                           float* __restrict__ C) {
    extern __shared__ char smem[];
    uint32_t sb = smem_u32(smem);
    int tid = threadIdx.x, warp = tid >> 5, lane = tid & 31;
    int bm = blockIdx.y * GBM, bn = blockIdx.x * GBN;
    int wm = (warp >> 2) * 64;   // 2 warps along M
    int wn = (warp & 3) * 32;    // 4 warps along N

    float acc[4][4][4];
#pragma unroll
    for (int i = 0; i < 4; i++)
#pragma unroll
        for (int j = 0; j < 4; j++)
#pragma unroll
            for (int k = 0; k < 4; k++) acc[i][j][k] = 0.f;

    auto load_stage = [&](int s, int ki) {
        uint32_t sA = sb + s * STAGE_BYTES;
        uint32_t sB = sA + GBM * GBK * 2;
        int k0 = ki * GBK;
#pragma unroll
        for (int j = 0; j < 4; j++) {
            int c = tid + j * 256;
            int row = c >> 3, cc = c & 7;
            cpasync16(sA + swz(row * 128 + cc * 16),
                      A + (size_t)(bm + row) * IN_DIM + k0 + cc * 8);
        }
#pragma unroll
        for (int j = 0; j < 4; j++) {
            int c = tid + j * 256;
            int row = c >> 3, cc = c & 7;
            cpasync16(sB + swz(row * 128 + cc * 16),
                      Bm + (size_t)(bn + row) * IN_DIM + k0 + cc * 8);
        }
        asm volatile("cp.async.commit_group;\n");
    };

    load_stage(0, 0);
    load_stage(1, 1);

    int rl = lane & 15, chh = (lane >> 4) * 16;
    int cur = 0;
    for (int i = 0; i < KT; i++) {
        asm volatile("cp.async.wait_group 1;\n");
        __syncthreads();
        if (i + 2 < KT) {
            int nxt = cur + 2; if (nxt >= NSTAGE) nxt -= NSTAGE;
            load_stage(nxt, i + 2);
        }

        uint32_t sA = sb + cur * STAGE_BYTES;
        uint32_t sB = sA + GBM * GBK * 2;
#pragma unroll
        for (int ks = 0; ks < 4; ks++) {
            uint32_t a[4][4], b[2][4];
#pragma unroll
            for (int mt = 0; mt < 4; mt++)
                ldsm_x4(a[mt], sA + swz((wm + mt * 16 + rl) * 128 + ks * 32 + chh));
#pragma unroll
            for (int ng = 0; ng < 2; ng++)
                ldsm_x4(b[ng], sB + swz((wn + ng * 16 + rl) * 128 + ks * 32 + chh));
#pragma unroll
            for (int mt = 0; mt < 4; mt++)
#pragma unroll
                for (int ng = 0; ng < 2; ng++) {
                    mma_bf16(acc[mt][2 * ng + 0], a[mt], b[ng][0], b[ng][2]);
                    mma_bf16(acc[mt][2 * ng + 1], a[mt], b[ng][1], b[ng][3]);
                }
        }
        cur = (cur + 1 == NSTAGE) ? 0 : cur + 1;
    }

    float* outp = C + (size_t)bm * F_DIM + bn;
#pragma unroll
    for (int mt = 0; mt < 4; mt++)
#pragma unroll
        for (int nt = 0; nt < 4; nt++) {
            int row = wm + mt * 16 + (lane >> 2);
            int col = wn + nt * 8 + (lane & 3) * 2;
            *(float2*)&outp[(size_t)row * F_DIM + col] =
                make_float2(acc[mt][nt][0], acc[mt][nt][1]);
            *(float2*)&outp[(size_t)(row + 8) * F_DIM + col] =
                make_float2(acc[mt][nt][2], acc[mt][nt][3]);
        }
}

// ===========================================================================
// Host launcher (serial — fork-join measured neutral)
// ===========================================================================
extern "C" void kernel_launch(void* const* d_in, const int* in_sizes, int n_in,
                              void* d_out, int out_size) {
    const float* x       = (const float*)d_in[0];  // [4096, 2048]
    const float* w       = (const float*)d_in[1];  // [2048, 4096]
    const float* bias    = (const float*)d_in[2];  // [4096]
    const float* noise_x = (const float*)d_in[5];  // [4096, 2048]
    const float* noise_w = (const float*)d_in[6];  // [2048, 4096]
    float* out = (float*)d_out;                    // [4096, 4096]

    float*         xr_p = nullptr;
    float*         wr_p = nullptr;
    __nv_bfloat16* xq_p = nullptr;
    __nv_bfloat16* wq_p = nullptr;
    float*         yr_p = nullptr;
    cudaGetSymbolAddress((void**)&xr_p, g_xr);
    cudaGetSymbolAddress((void**)&wr_p, g_wr);
    cudaGetSymbolAddress((void**)&xq_p, g_xq);
    cudaGetSymbolAddress((void**)&wq_p, g_wqT);
    cudaGetSymbolAddress((void**)&yr_p, g_yr);

    const int CW_SMEM = 4096 * 8 * sizeof(float);  // 128 KB
    const int RW_SMEM = 2 * 2 * 4096 * sizeof(float);  // 64 KB
    cudaFuncSetAttribute(gemm_bf16_kernel, cudaFuncAttributeMaxDynamicSharedMemorySize,
                         GEMM_SMEM);
    cudaFuncSetAttribute(colwht_fused8_kernel<true, false>,
                         cudaFuncAttributeMaxDynamicSharedMemorySize, CW_SMEM);
    cudaFuncSetAttribute(colwht_fused8_kernel<false, true>,
                         cudaFuncAttributeMaxDynamicSharedMemorySize, CW_SMEM);
    cudaFuncSetAttribute(rowwht_pipe_kernel<true>,
                         cudaFuncAttributeMaxDynamicSharedMemorySize, RW_SMEM);
    cudaFuncSetAttribute(rowwht_pipe_kernel<false>,
                         cudaFuncAttributeMaxDynamicSharedMemorySize, RW_SMEM);

    init_kernel<<<1, 1>>>();

    // xr = WHT_batch(x): both radix-64 passes fused, with global max
    colwht_fused8_kernel<true, false><<<IN_DIM / 8, 512, CW_SMEM>>>(x, xr_p, IN_DIM, nullptr);
    quantx_kernel<<<(B_DIM * IN_DIM / 4 + 255) / 256, 256>>>(xr_p, noise_x, xq_p,
                                                             B_DIM * IN_DIM / 4);

    // wr = WHT_features(w), fused max; quantize + transpose to [F][IN]
    rowwht_pipe_kernel<true><<<IN_DIM / 8, 128, RW_SMEM>>>(w, wr_p);
    quantw_transpose_kernel<<<dim3(F_DIM / 32, IN_DIM / 32), dim3(32, 8)>>>(wr_p, noise_w, wq_p);

    // pipelined bf16 HMMA GEMM -> float (exact integer arithmetic)
    gemm_bf16_kernel<<<dim3(F_DIM / GBN, B_DIM / GBM), 256, GEMM_SMEM>>>(xq_p, wq_p, yr_p);

    // inverse rotations: pipelined rows, then fused column pair w/ scale+bias
    rowwht_pipe_kernel<false><<<B_DIM / 8, 128, RW_SMEM>>>(yr_p, yr_p);
    colwht_fused8_kernel<false, true><<<F_DIM / 8, 512, CW_SMEM>>>(yr_p, out, F_DIM, bias);
}

// round 15
// speedup vs baseline: 1.0422x; 1.0422x over previous
#include <cuda_runtime.h>
#include <cuda_bf16.h>
#include <cstdint>

#define B_DIM 4096
#define IN_DIM 2048
#define F_DIM 4096

// ---------------------------------------------------------------------------
// Scratch (device globals: no allocation allowed)
// ---------------------------------------------------------------------------
__device__ float          g_xr[B_DIM * IN_DIM];    // rotated activations (fp32 — REQUIRED)
__device__ float          g_wr[IN_DIM * F_DIM];    // rotated weights (fp32 — REQUIRED)
__device__ __nv_bfloat16  g_xq[B_DIM * IN_DIM];    // quantized activations [M][K]
__device__ __nv_bfloat16  g_wqT[F_DIM * IN_DIM];   // quantized weights TRANSPOSED [N][K]
__device__ float          g_yr[B_DIM * F_DIM];     // GEMM result (float, exact ints)
__device__ int            g_maxx_bits;
__device__ int            g_maxw_bits;

// ===========================================================================
// Helpers
// ===========================================================================
__device__ __forceinline__ uint32_t smem_u32(const void* p) {
    uint32_t a;
    asm("{ .reg .u64 t; cvta.to.shared.u64 t, %1; cvt.u32.u64 %0, t; }" : "=r"(a) : "l"(p));
    return a;
}

__device__ __forceinline__ void cpasync16(uint32_t dst, const void* src) {
    asm volatile("cp.async.cg.shared.global [%0], [%1], 16;\n" :: "r"(dst), "l"(src));
}

// Swizzle<3,4,3>: XOR 16B-chunk bits [6:4] with 128B-line bits [9:7]
__device__ __forceinline__ uint32_t swz(uint32_t o) { return o ^ (((o >> 7) & 7) << 4); }

__device__ __forceinline__ void ldsm_x4(uint32_t r[4], uint32_t addr) {
    asm volatile("ldmatrix.sync.aligned.m8n8.x4.shared.b16 {%0,%1,%2,%3}, [%4];"
                 : "=r"(r[0]), "=r"(r[1]), "=r"(r[2]), "=r"(r[3]) : "r"(addr));
}

__device__ __forceinline__ void mma_bf16(float c[4], const uint32_t a[4], uint32_t b0, uint32_t b1) {
    asm volatile(
        "mma.sync.aligned.m16n8k16.row.col.f32.bf16.bf16.f32 "
        "{%0,%1,%2,%3}, {%4,%5,%6,%7}, {%8,%9}, {%0,%1,%2,%3};"
        : "+f"(c[0]), "+f"(c[1]), "+f"(c[2]), "+f"(c[3])
        : "r"(a[0]), "r"(a[1]), "r"(a[2]), "r"(a[3]), "r"(b0), "r"(b1));
}

// ===========================================================================
// WHT primitives
// ===========================================================================
__device__ __forceinline__ void wht64(float v[64]) {
#pragma unroll
    for (int s = 1; s < 64; s <<= 1) {
#pragma unroll
        for (int i = 0; i < 64; i++) {
            if ((i & s) == 0) {
                float a = v[i], b = v[i + s];
                v[i]     = a + b;
                v[i + s] = a - b;
            }
        }
    }
}

__global__ void init_kernel() {
    g_maxx_bits = 0;
    g_maxw_bits = 0;
}

// ---------------------------------------------------------------------------
// FUSED column-axis WHT-4096: both radix-64 passes in one kernel.
// Block: 512 threads, 8 columns, all 4096 rows resident in 128 KB smem.
// All gmem accesses are 32B-aligned 32B runs -> 100% sector utilization.
// ---------------------------------------------------------------------------
#define FSWZ(a) ((a) ^ ((((a) >> 9) & 3) << 3))

template <bool DO_MAX, bool FINAL>
__global__ __launch_bounds__(512) void colwht_fused8_kernel(const float* __restrict__ in,
                                                            float* __restrict__ out,
                                                            int ncols,
                                                            const float* __restrict__ bias) {
    extern __shared__ float sm[];   // 4096 rows x 8 cols, swizzled (128 KB)
    int tid  = threadIdx.x;
    int col0 = blockIdx.x * 8;

    // Load: 8192 float4s (2 per row), fully coalesced
#pragma unroll
    for (int j = 0; j < 16; j++) {
        int i = tid + j * 512;
        int r = i >> 1, q = i & 1;
        float4 v = *(const float4*)&in[(size_t)r * ncols + col0 + q * 4];
        *(float4*)&sm[FSWZ(r * 8 + q * 4)] = v;
    }
    __syncthreads();

    int g = tid >> 3, c = tid & 7;         // thread owns (group g, local col c)
    float v[64];

    // pass 1: rows g*64 + k (stride 1)
#pragma unroll
    for (int k = 0; k < 64; k++) v[k] = sm[FSWZ((g * 64 + k) * 8 + c)];
    wht64(v);
#pragma unroll
    for (int k = 0; k < 64; k++) sm[FSWZ((g * 64 + k) * 8 + c)] = v[k];
    __syncthreads();

    // pass 2: rows g + 64k (stride 64)
#pragma unroll
    for (int k = 0; k < 64; k++) v[k] = sm[FSWZ((g + 64 * k) * 8 + c)];
    wht64(v);

    if (DO_MAX) {
        float m = 0.f;
#pragma unroll
        for (int k = 0; k < 64; k++) m = fmaxf(m, fabsf(v[k]));
#pragma unroll
        for (int off = 16; off; off >>= 1)
            m = fmaxf(m, __shfl_xor_sync(0xffffffffu, m, off));
        if ((tid & 31) == 0) atomicMax(&g_maxx_bits, __float_as_int(m));
    }

    float scale = 1.f, bv = 0.f;
    if (FINAL) {
        float mx = __int_as_float(g_maxx_bits);
        float mw = __int_as_float(g_maxw_bits);
        scale = (mx / 127.f) * (mw / 127.f) * 0x1p-24f;
        bv    = bias[col0 + c];
    }
    // writeout: per warp 4 rows x 8 consecutive floats = 32B runs
#pragma unroll
    for (int k = 0; k < 64; k++) {
        size_t idx = (size_t)(g + 64 * k) * ncols + col0 + c;
        out[idx] = FINAL ? (v[k] * scale + bv) : v[k];
    }
}

// ---------------------------------------------------------------------------
// Row-axis WHT (contiguous dim 4096) with coalesced writeout
// ---------------------------------------------------------------------------
template <bool DO_MAXW>
__global__ __launch_bounds__(128) void rowwht_kernel(const float* __restrict__ in,
                                                     float* __restrict__ out) {
    __shared__ float sm[2][4096];
    int g   = threadIdx.x >> 6;
    int t   = threadIdx.x & 63;
    int row = blockIdx.x * 2 + g;

    float v[64];
#pragma unroll
    for (int k = 0; k < 64; k++) v[k] = in[(size_t)row * 4096 + t + (k << 6)];
    wht64(v);
#pragma unroll
    for (int k = 0; k < 64; k++) {
        int a = t + (k << 6);
        sm[g][a ^ ((a >> 6) & 31)] = v[k];
    }
    __syncthreads();
#pragma unroll
    for (int k = 0; k < 64; k++) {
        int a = (t << 6) + k;
        v[k] = sm[g][a ^ ((a >> 6) & 31)];
    }
    wht64(v);

    if (DO_MAXW) {
        float m = 0.f;
#pragma unroll
        for (int k = 0; k < 64; k++) m = fmaxf(m, fabsf(v[k]));
#pragma unroll
        for (int off = 16; off; off >>= 1)
            m = fmaxf(m, __shfl_xor_sync(0xffffffffu, m, off));
        if ((threadIdx.x & 31) == 0) atomicMax(&g_maxw_bits, __float_as_int(m));
    }

    __syncthreads();
#pragma unroll
    for (int k = 0; k < 64; k++) {
        int a = (t << 6) + k;
        sm[g][a ^ ((a >> 6) & 31)] = v[k];
    }
    __syncthreads();

    size_t base = (size_t)blockIdx.x * 2 * 4096;
#pragma unroll
    for (int i = 0; i < 64; i++) {
        int lin = threadIdx.x + i * 128;
        int gg  = lin >> 12;
        int a   = lin & 4095;
        out[base + lin] = sm[gg][a ^ ((a >> 6) & 31)];
    }
}

// ===========================================================================
// Quantization (fp32 in, bf16 integer-valued out)
// ===========================================================================
__device__ __forceinline__ float stoch_q(float xv, float nv, float s) {
    float xs = xv / s;
    float f  = floorf(xs);
    float q  = f + ((nv < xs - f) ? 1.f : 0.f);
    return fminf(127.f, fmaxf(-127.f, q));
}

__global__ __launch_bounds__(256) void quantx_kernel(const float* __restrict__ xr,
                                                     const float* __restrict__ noise,
                                                     __nv_bfloat16* __restrict__ qo,
                                                     int n4) {
    int i = blockIdx.x * blockDim.x + threadIdx.x;
    if (i >= n4) return;
    float s = __int_as_float(g_maxx_bits) / 127.f;
    float4 x  = ((const float4*)xr)[i];
    float4 nz = ((const float4*)noise)[i];
    __nv_bfloat162 lo = __floats2bfloat162_rn(stoch_q(x.x, nz.x, s), stoch_q(x.y, nz.y, s));
    __nv_bfloat162 hi = __floats2bfloat162_rn(stoch_q(x.z, nz.z, s), stoch_q(x.w, nz.w, s));
    uint2 o;
    o.x = *(uint32_t*)&lo;
    o.y = *(uint32_t*)&hi;
    ((uint2*)qo)[i] = o;
}

// weights: quantize + transpose [IN][F] -> [F][IN] bf16 (K-major B operand)
__global__ __launch_bounds__(256) void quantw_transpose_kernel(const float* __restrict__ wr,
                                                               const float* __restrict__ noise,
                                                               __nv_bfloat16* __restrict__ qoT) {
    __shared__ __nv_bfloat16 t[32][33];
    float s = __int_as_float(g_maxw_bits) / 127.f;
    int x  = blockIdx.x * 32 + threadIdx.x;   // F index
    int y0 = blockIdx.y * 32;                 // IN base
#pragma unroll
    for (int j = 0; j < 4; j++) {
        int y   = y0 + threadIdx.y + j * 8;
        int idx = y * F_DIM + x;
        t[threadIdx.y + j * 8][threadIdx.x] = __float2bfloat16(stoch_q(wr[idx], noise[idx], s));
    }
    __syncthreads();
#pragma unroll
    for (int j = 0; j < 4; j++) {
        int fo = blockIdx.x * 32 + threadIdx.y + j * 8;
        qoT[(size_t)fo * IN_DIM + y0 + threadIdx.x] = t[threadIdx.x][threadIdx.y + j * 8];
    }
}

// ===========================================================================
// Pipelined bf16 GEMM (HMMA), PROVEN config: CTA 128x128, 8 warps (2x4),
// warp tile 64x32, BK=64 (128B rows, SW), 3-stage cp.async, 2 CTAs/SM.
// ===========================================================================
#define GBM 128
#define GBN 128
#define GBK 64
#define NSTAGE 3
#define KT (IN_DIM / GBK)                          // 32
#define STAGE_BYTES ((GBM + GBN) * GBK * 2)        // 32768
#define GEMM_SMEM (NSTAGE * STAGE_BYTES)           // 98304

__global__ __launch_bounds__(256, 2) void gemm_bf16_kernel(const __nv_bfloat16* __restrict__ A,
                                                           const __nv_bfloat16* __restrict__ Bm,
                                                           float* __restrict__ C) {
    extern __shared__ char smem[];
    uint32_t sb = smem_u32(smem);
    int tid = threadIdx.x, warp = tid >> 5, lane = tid & 31;
    int bm = blockIdx.y * GBM, bn = blockIdx.x * GBN;
    int wm = (warp >> 2) * 64;   // 2 warps along M
    int wn = (warp & 3) * 32;    // 4 warps along N

    float acc[4][4][4];
#pragma unroll
    for (int i = 0; i < 4; i++)
#pragma unroll
        for (int j = 0; j < 4; j++)
#pragma unroll
            for (int k = 0; k < 4; k++) acc[i][j][k] = 0.f;

    auto load_stage = [&](int s, int ki) {
        uint32_t sA = sb + s * STAGE_BYTES;
        uint32_t sB = sA + GBM * GBK * 2;
        int k0 = ki * GBK;
#pragma unroll
        for (int j = 0; j < 4; j++) {
            int c = tid + j * 256;
            int row = c >> 3, cc = c & 7;
            cpasync16(sA + swz(row * 128 + cc * 16),
                      A + (size_t)(bm + row) * IN_DIM + k0 + cc * 8);
        }
#pragma unroll
        for (int j = 0; j < 4; j++) {
            int c = tid + j * 256;
            int row = c >> 3, cc = c & 7;
            cpasync16(sB + swz(row * 128 + cc * 16),
                      Bm + (size_t)(bn + row) * IN_DIM + k0 + cc * 8);
        }
        asm volatile("cp.async.commit_group;\n");
    };

    load_stage(0, 0);
    load_stage(1, 1);

    int rl = lane & 15, chh = (lane >> 4) * 16;
    int cur = 0;
    for (int i = 0; i < KT; i++) {
        asm volatile("cp.async.wait_group 1;\n");
        __syncthreads();
        if (i + 2 < KT) {
            int nxt = cur + 2; if (nxt >= NSTAGE) nxt -= NSTAGE;
            load_stage(nxt, i + 2);
        }

        uint32_t sA = sb + cur * STAGE_BYTES;
        uint32_t sB = sA + GBM * GBK * 2;
#pragma unroll
        for (int ks = 0; ks < 4; ks++) {
            uint32_t a[4][4], b[2][4];
#pragma unroll
            for (int mt = 0; mt < 4; mt++)
                ldsm_x4(a[mt], sA + swz((wm + mt * 16 + rl) * 128 + ks * 32 + chh));
#pragma unroll
            for (int ng = 0; ng < 2; ng++)
                ldsm_x4(b[ng], sB + swz((wn + ng * 16 + rl) * 128 + ks * 32 + chh));
#pragma unroll
            for (int mt = 0; mt < 4; mt++)
#pragma unroll
                for (int ng = 0; ng < 2; ng++) {
                    mma_bf16(acc[mt][2 * ng + 0], a[mt], b[ng][0], b[ng][2]);
                    mma_bf16(acc[mt][2 * ng + 1], a[mt], b[ng][1], b[ng][3]);
                }
        }
        cur = (cur + 1 == NSTAGE) ? 0 : cur + 1;
    }

    float* outp = C + (size_t)bm * F_DIM + bn;
#pragma unroll
    for (int mt = 0; mt < 4; mt++)
#pragma unroll
        for (int nt = 0; nt < 4; nt++) {
            int row = wm + mt * 16 + (lane >> 2);
            int col = wn + nt * 8 + (lane & 3) * 2;
            *(float2*)&outp[(size_t)row * F_DIM + col] =
                make_float2(acc[mt][nt][0], acc[mt][nt][1]);
            *(float2*)&outp[(size_t)(row + 8) * F_DIM + col] =
                make_float2(acc[mt][nt][2], acc[mt][nt][3]);
        }
}

// ===========================================================================
// Host launcher
// ===========================================================================
extern "C" void kernel_launch(void* const* d_in, const int* in_sizes, int n_in,
                              void* d_out, int out_size) {
    const float* x       = (const float*)d_in[0];  // [4096, 2048]
    const float* w       = (const float*)d_in[1];  // [2048, 4096]
    const float* bias    = (const float*)d_in[2];  // [4096]
    const float* noise_x = (const float*)d_in[5];  // [4096, 2048]
    const float* noise_w = (const float*)d_in[6];  // [2048, 4096]
    float* out = (float*)d_out;                    // [4096, 4096]

    float*         xr_p = nullptr;
    float*         wr_p = nullptr;
    __nv_bfloat16* xq_p = nullptr;
    __nv_bfloat16* wq_p = nullptr;
    float*         yr_p = nullptr;
    cudaGetSymbolAddress((void**)&xr_p, g_xr);
    cudaGetSymbolAddress((void**)&wr_p, g_wr);
    cudaGetSymbolAddress((void**)&xq_p, g_xq);
    cudaGetSymbolAddress((void**)&wq_p, g_wqT);
    cudaGetSymbolAddress((void**)&yr_p, g_yr);

    const int CW_SMEM = 4096 * 8 * sizeof(float);  // 128 KB
    cudaFuncSetAttribute(gemm_bf16_kernel, cudaFuncAttributeMaxDynamicSharedMemorySize,
                         GEMM_SMEM);
    cudaFuncSetAttribute(colwht_fused8_kernel<true, false>,
                         cudaFuncAttributeMaxDynamicSharedMemorySize, CW_SMEM);
    cudaFuncSetAttribute(colwht_fused8_kernel<false, true>,
                         cudaFuncAttributeMaxDynamicSharedMemorySize, CW_SMEM);

    init_kernel<<<1, 1>>>();

    // xr = WHT_batch(x): both radix-64 passes fused, with global max
    colwht_fused8_kernel<true, false><<<IN_DIM / 8, 512, CW_SMEM>>>(x, xr_p, IN_DIM, nullptr);
    quantx_kernel<<<(B_DIM * IN_DIM / 4 + 255) / 256, 256>>>(xr_p, noise_x, xq_p,
                                                             B_DIM * IN_DIM / 4);

    // wr = WHT_features(w), fused max; quantize + transpose to [F][IN]
    rowwht_kernel<true><<<IN_DIM / 2, 128>>>(w, wr_p);
    quantw_transpose_kernel<<<dim3(F_DIM / 32, IN_DIM / 32), dim3(32, 8)>>>(wr_p, noise_w, wq_p);

    // pipelined bf16 HMMA GEMM -> float (exact integer arithmetic)
    gemm_bf16_kernel<<<dim3(F_DIM / GBN, B_DIM / GBM), 256, GEMM_SMEM>>>(xq_p, wq_p, yr_p);

    // inverse rotations: rows, then fused column pair with scale+bias -> out
    rowwht_kernel<false><<<B_DIM / 2, 128>>>(yr_p, yr_p);
    colwht_fused8_kernel<false, true><<<F_DIM / 8, 512, CW_SMEM>>>(yr_p, out, F_DIM, bias);
}

// round 16
// speedup vs baseline: 1.0425x; 1.0003x over previous
#include <cuda_runtime.h>
#include <cuda_fp16.h>
#include <cstdint>

#define B_DIM 4096
#define IN_DIM 2048
#define F_DIM 4096

// ---------------------------------------------------------------------------
// Scratch (device globals: no allocation allowed)
// ---------------------------------------------------------------------------
__device__ float   g_xr[B_DIM * IN_DIM];    // rotated activations (fp32 — REQUIRED)
__device__ float   g_wr[IN_DIM * F_DIM];    // rotated weights (fp32 — REQUIRED)
__device__ __half  g_xq[B_DIM * IN_DIM];    // quantized activations [M][K] (fp16 ints)
__device__ __half  g_wqT[F_DIM * IN_DIM];   // quantized weights TRANSPOSED [N][K]
__device__ float   g_yr[B_DIM * F_DIM];     // GEMM result (float, exact ints)
__device__ int     g_maxx_bits;
__device__ int     g_maxw_bits;

// ===========================================================================
// Helpers
// ===========================================================================
__device__ __forceinline__ uint32_t smem_u32(const void* p) {
    uint32_t a;
    asm("{ .reg .u64 t; cvta.to.shared.u64 t, %1; cvt.u32.u64 %0, t; }" : "=r"(a) : "l"(p));
    return a;
}

__device__ __forceinline__ void cpasync16(uint32_t dst, const void* src) {
    asm volatile("cp.async.cg.shared.global [%0], [%1], 16;\n" :: "r"(dst), "l"(src));
}

// Swizzle<3,4,3>: XOR 16B-chunk bits [6:4] with 128B-line bits [9:7]
__device__ __forceinline__ uint32_t swz(uint32_t o) { return o ^ (((o >> 7) & 7) << 4); }

__device__ __forceinline__ void ldsm_x4(uint32_t r[4], uint32_t addr) {
    asm volatile("ldmatrix.sync.aligned.m8n8.x4.shared.b16 {%0,%1,%2,%3}, [%4];"
                 : "=r"(r[0]), "=r"(r[1]), "=r"(r[2]), "=r"(r[3]) : "r"(addr));
}

// fp16 operands, fp32 accumulate — exact for integer-valued ±127 operands
__device__ __forceinline__ void mma_f16(float c[4], const uint32_t a[4], uint32_t b0, uint32_t b1) {
    asm volatile(
        "mma.sync.aligned.m16n8k16.row.col.f32.f16.f16.f32 "
        "{%0,%1,%2,%3}, {%4,%5,%6,%7}, {%8,%9}, {%0,%1,%2,%3};"
        : "+f"(c[0]), "+f"(c[1]), "+f"(c[2]), "+f"(c[3])
        : "r"(a[0]), "r"(a[1]), "r"(a[2]), "r"(a[3]), "r"(b0), "r"(b1));
}

// ===========================================================================
// WHT primitives
// ===========================================================================
__device__ __forceinline__ void wht64(float v[64]) {
#pragma unroll
    for (int s = 1; s < 64; s <<= 1) {
#pragma unroll
        for (int i = 0; i < 64; i++) {
            if ((i & s) == 0) {
                float a = v[i], b = v[i + s];
                v[i]     = a + b;
                v[i + s] = a - b;
            }
        }
    }
}

__global__ void init_kernel() {
    g_maxx_bits = 0;
    g_maxw_bits = 0;
}

// ---------------------------------------------------------------------------
// FUSED column-axis WHT-4096 (8 cols / 512 threads / 128 KB smem)
// ---------------------------------------------------------------------------
#define FSWZ(a) ((a) ^ ((((a) >> 9) & 3) << 3))

template <bool DO_MAX, bool FINAL>
__global__ __launch_bounds__(512) void colwht_fused8_kernel(const float* __restrict__ in,
                                                            float* __restrict__ out,
                                                            int ncols,
                                                            const float* __restrict__ bias) {
    extern __shared__ float sm[];
    int tid  = threadIdx.x;
    int col0 = blockIdx.x * 8;

#pragma unroll
    for (int j = 0; j < 16; j++) {
        int i = tid + j * 512;
        int r = i >> 1, q = i & 1;
        float4 v = *(const float4*)&in[(size_t)r * ncols + col0 + q * 4];
        *(float4*)&sm[FSWZ(r * 8 + q * 4)] = v;
    }
    __syncthreads();

    int g = tid >> 3, c = tid & 7;
    float v[64];

#pragma unroll
    for (int k = 0; k < 64; k++) v[k] = sm[FSWZ((g * 64 + k) * 8 + c)];
    wht64(v);
#pragma unroll
    for (int k = 0; k < 64; k++) sm[FSWZ((g * 64 + k) * 8 + c)] = v[k];
    __syncthreads();

#pragma unroll
    for (int k = 0; k < 64; k++) v[k] = sm[FSWZ((g + 64 * k) * 8 + c)];
    wht64(v);

    if (DO_MAX) {
        float m = 0.f;
#pragma unroll
        for (int k = 0; k < 64; k++) m = fmaxf(m, fabsf(v[k]));
#pragma unroll
        for (int off = 16; off; off >>= 1)
            m = fmaxf(m, __shfl_xor_sync(0xffffffffu, m, off));
        if ((tid & 31) == 0) atomicMax(&g_maxx_bits, __float_as_int(m));
    }

    float scale = 1.f, bv = 0.f;
    if (FINAL) {
        float mx = __int_as_float(g_maxx_bits);
        float mw = __int_as_float(g_maxw_bits);
        scale = (mx / 127.f) * (mw / 127.f) * 0x1p-24f;
        bv    = bias[col0 + c];
    }
#pragma unroll
    for (int k = 0; k < 64; k++) {
        size_t idx = (size_t)(g + 64 * k) * ncols + col0 + c;
        out[idx] = FINAL ? (v[k] * scale + bv) : v[k];
    }
}

// ---------------------------------------------------------------------------
// Row-axis WHT (contiguous dim 4096) with coalesced writeout
// ---------------------------------------------------------------------------
template <bool DO_MAXW>
__global__ __launch_bounds__(128) void rowwht_kernel(const float* __restrict__ in,
                                                     float* __restrict__ out) {
    __shared__ float sm[2][4096];
    int g   = threadIdx.x >> 6;
    int t   = threadIdx.x & 63;
    int row = blockIdx.x * 2 + g;

    float v[64];
#pragma unroll
    for (int k = 0; k < 64; k++) v[k] = in[(size_t)row * 4096 + t + (k << 6)];
    wht64(v);
#pragma unroll
    for (int k = 0; k < 64; k++) {
        int a = t + (k << 6);
        sm[g][a ^ ((a >> 6) & 31)] = v[k];
    }
    __syncthreads();
#pragma unroll
    for (int k = 0; k < 64; k++) {
        int a = (t << 6) + k;
        v[k] = sm[g][a ^ ((a >> 6) & 31)];
    }
    wht64(v);

    if (DO_MAXW) {
        float m = 0.f;
#pragma unroll
        for (int k = 0; k < 64; k++) m = fmaxf(m, fabsf(v[k]));
#pragma unroll
        for (int off = 16; off; off >>= 1)
            m = fmaxf(m, __shfl_xor_sync(0xffffffffu, m, off));
        if ((threadIdx.x & 31) == 0) atomicMax(&g_maxw_bits, __float_as_int(m));
    }

    __syncthreads();
#pragma unroll
    for (int k = 0; k < 64; k++) {
        int a = (t << 6) + k;
        sm[g][a ^ ((a >> 6) & 31)] = v[k];
    }
    __syncthreads();

    size_t base = (size_t)blockIdx.x * 2 * 4096;
#pragma unroll
    for (int i = 0; i < 64; i++) {
        int lin = threadIdx.x + i * 128;
        int gg  = lin >> 12;
        int a   = lin & 4095;
        out[base + lin] = sm[gg][a ^ ((a >> 6) & 31)];
    }
}

// ===========================================================================
// Quantization (fp32 in, fp16 integer-valued out)
// ===========================================================================
__device__ __forceinline__ float stoch_q(float xv, float nv, float s) {
    float xs = xv / s;
    float f  = floorf(xs);
    float q  = f + ((nv < xs - f) ? 1.f : 0.f);
    return fminf(127.f, fmaxf(-127.f, q));
}

__global__ __launch_bounds__(256) void quantx_kernel(const float* __restrict__ xr,
                                                     const float* __restrict__ noise,
                                                     __half* __restrict__ qo,
                                                     int n4) {
    int i = blockIdx.x * blockDim.x + threadIdx.x;
    if (i >= n4) return;
    float s = __int_as_float(g_maxx_bits) / 127.f;
    float4 x  = ((const float4*)xr)[i];
    float4 nz = ((const float4*)noise)[i];
    __half2 lo = __floats2half2_rn(stoch_q(x.x, nz.x, s), stoch_q(x.y, nz.y, s));
    __half2 hi = __floats2half2_rn(stoch_q(x.z, nz.z, s), stoch_q(x.w, nz.w, s));
    uint2 o;
    o.x = *(uint32_t*)&lo;
    o.y = *(uint32_t*)&hi;
    ((uint2*)qo)[i] = o;
}

// weights: quantize + transpose [IN][F] -> [F][IN] fp16 (K-major B operand)
__global__ __launch_bounds__(256) void quantw_transpose_kernel(const float* __restrict__ wr,
                                                               const float* __restrict__ noise,
                                                               __half* __restrict__ qoT) {
    __shared__ __half t[32][33];
    float s = __int_as_float(g_maxw_bits) / 127.f;
    int x  = blockIdx.x * 32 + threadIdx.x;   // F index
    int y0 = blockIdx.y * 32;                 // IN base
#pragma unroll
    for (int j = 0; j < 4; j++) {
        int y   = y0 + threadIdx.y + j * 8;
        int idx = y * F_DIM + x;
        t[threadIdx.y + j * 8][threadIdx.x] = __float2half_rn(stoch_q(wr[idx], noise[idx], s));
    }
    __syncthreads();
#pragma unroll
    for (int j = 0; j < 4; j++) {
        int fo = blockIdx.x * 32 + threadIdx.y + j * 8;
        qoT[(size_t)fo * IN_DIM + y0 + threadIdx.x] = t[threadIdx.x][threadIdx.y + j * 8];
    }
}

// ===========================================================================
// Pipelined fp16 GEMM (HMMA): CTA 128x128, 8 warps (2x4), warp tile 64x32,
// BK=64 (128B rows, SW), 3-stage cp.async, 2 CTAs/SM.
// ===========================================================================
#define GBM 128
#define GBN 128
#define GBK 64
#define NSTAGE 3
#define KT (IN_DIM / GBK)                          // 32
#define STAGE_BYTES ((GBM + GBN) * GBK * 2)        // 32768
#define GEMM_SMEM (NSTAGE * STAGE_BYTES)           // 98304

__global__ __launch_bounds__(256, 2) void gemm_f16_kernel(const __half* __restrict__ A,
                                                          const __half* __restrict__ Bm,
                                                          float* __restrict__ C) {
    extern __shared__ char smem[];
    uint32_t sb = smem_u32(smem);
    int tid = threadIdx.x, warp = tid >> 5, lane = tid & 31;
    int bm = blockIdx.y * GBM, bn = blockIdx.x * GBN;
    int wm = (warp >> 2) * 64;   // 2 warps along M
    int wn = (warp & 3) * 32;    // 4 warps along N

    float acc[4][4][4];
#pragma unroll
    for (int i = 0; i < 4; i++)
#pragma unroll
        for (int j = 0; j < 4; j++)
#pragma unroll
            for (int k = 0; k < 4; k++) acc[i][j][k] = 0.f;

    auto load_stage = [&](int s, int ki) {
        uint32_t sA = sb + s * STAGE_BYTES;
        uint32_t sB = sA + GBM * GBK * 2;
        int k0 = ki * GBK;
#pragma unroll
        for (int j = 0; j < 4; j++) {
            int c = tid + j * 256;
            int row = c >> 3, cc = c & 7;
            cpasync16(sA + swz(row * 128 + cc * 16),
                      A + (size_t)(bm + row) * IN_DIM + k0 + cc * 8);
        }
#pragma unroll
        for (int j = 0; j < 4; j++) {
            int c = tid + j * 256;
            int row = c >> 3, cc = c & 7;
            cpasync16(sB + swz(row * 128 + cc * 16),
                      Bm + (size_t)(bn + row) * IN_DIM + k0 + cc * 8);
        }
        asm volatile("cp.async.commit_group;\n");
    };

    load_stage(0, 0);
    load_stage(1, 1);

    int rl = lane & 15, chh = (lane >> 4) * 16;
    int cur = 0;
    for (int i = 0; i < KT; i++) {
        asm volatile("cp.async.wait_group 1;\n");
        __syncthreads();
        if (i + 2 < KT) {
            int nxt = cur + 2; if (nxt >= NSTAGE) nxt -= NSTAGE;
            load_stage(nxt, i + 2);
        }

        uint32_t sA = sb + cur * STAGE_BYTES;
        uint32_t sB = sA + GBM * GBK * 2;
#pragma unroll
        for (int ks = 0; ks < 4; ks++) {
            uint32_t a[4][4], b[2][4];
#pragma unroll
            for (int mt = 0; mt < 4; mt++)
                ldsm_x4(a[mt], sA + swz((wm + mt * 16 + rl) * 128 + ks * 32 + chh));
#pragma unroll
            for (int ng = 0; ng < 2; ng++)
                ldsm_x4(b[ng], sB + swz((wn + ng * 16 + rl) * 128 + ks * 32 + chh));
#pragma unroll
            for (int mt = 0; mt < 4; mt++)
#pragma unroll
                for (int ng = 0; ng < 2; ng++) {
                    mma_f16(acc[mt][2 * ng + 0], a[mt], b[ng][0], b[ng][2]);
                    mma_f16(acc[mt][2 * ng + 1], a[mt], b[ng][1], b[ng][3]);
                }
        }
        cur = (cur + 1 == NSTAGE) ? 0 : cur + 1;
    }

    float* outp = C + (size_t)bm * F_DIM + bn;
#pragma unroll
    for (int mt = 0; mt < 4; mt++)
#pragma unroll
        for (int nt = 0; nt < 4; nt++) {
            int row = wm + mt * 16 + (lane >> 2);
            int col = wn + nt * 8 + (lane & 3) * 2;
            *(float2*)&outp[(size_t)row * F_DIM + col] =
                make_float2(acc[mt][nt][0], acc[mt][nt][1]);
            *(float2*)&outp[(size_t)(row + 8) * F_DIM + col] =
                make_float2(acc[mt][nt][2], acc[mt][nt][3]);
        }
}

// ===========================================================================
// Host launcher
// ===========================================================================
extern "C" void kernel_launch(void* const* d_in, const int* in_sizes, int n_in,
                              void* d_out, int out_size) {
    const float* x       = (const float*)d_in[0];  // [4096, 2048]
    const float* w       = (const float*)d_in[1];  // [2048, 4096]
    const float* bias    = (const float*)d_in[2];  // [4096]
    const float* noise_x = (const float*)d_in[5];  // [4096, 2048]
    const float* noise_w = (const float*)d_in[6];  // [2048, 4096]
    float* out = (float*)d_out;                    // [4096, 4096]

    float*  xr_p = nullptr;
    float*  wr_p = nullptr;
    __half* xq_p = nullptr;
    __half* wq_p = nullptr;
    float*  yr_p = nullptr;
    cudaGetSymbolAddress((void**)&xr_p, g_xr);
    cudaGetSymbolAddress((void**)&wr_p, g_wr);
    cudaGetSymbolAddress((void**)&xq_p, g_xq);
    cudaGetSymbolAddress((void**)&wq_p, g_wqT);
    cudaGetSymbolAddress((void**)&yr_p, g_yr);

    const int CW_SMEM = 4096 * 8 * sizeof(float);  // 128 KB
    cudaFuncSetAttribute(gemm_f16_kernel, cudaFuncAttributeMaxDynamicSharedMemorySize,
                         GEMM_SMEM);
    cudaFuncSetAttribute(colwht_fused8_kernel<true, false>,
                         cudaFuncAttributeMaxDynamicSharedMemorySize, CW_SMEM);
    cudaFuncSetAttribute(colwht_fused8_kernel<false, true>,
                         cudaFuncAttributeMaxDynamicSharedMemorySize, CW_SMEM);

    init_kernel<<<1, 1>>>();

    // xr = WHT_batch(x): both radix-64 passes fused, with global max
    colwht_fused8_kernel<true, false><<<IN_DIM / 8, 512, CW_SMEM>>>(x, xr_p, IN_DIM, nullptr);
    quantx_kernel<<<(B_DIM * IN_DIM / 4 + 255) / 256, 256>>>(xr_p, noise_x, xq_p,
                                                             B_DIM * IN_DIM / 4);

    // wr = WHT_features(w), fused max; quantize + transpose to [F][IN]
    rowwht_kernel<true><<<IN_DIM / 2, 128>>>(w, wr_p);
    quantw_transpose_kernel<<<dim3(F_DIM / 32, IN_DIM / 32), dim3(32, 8)>>>(wr_p, noise_w, wq_p);

    // pipelined fp16 HMMA GEMM -> float (exact integer arithmetic)
    gemm_f16_kernel<<<dim3(F_DIM / GBN, B_DIM / GBM), 256, GEMM_SMEM>>>(xq_p, wq_p, yr_p);

    // inverse rotations: rows, then fused column pair with scale+bias -> out
    rowwht_kernel<false><<<B_DIM / 2, 128>>>(yr_p, yr_p);
    colwht_fused8_kernel<false, true><<<F_DIM / 8, 512, CW_SMEM>>>(yr_p, out, F_DIM, bias);
}